// round 6
// baseline (speedup 1.0000x reference)
#include <cuda_runtime.h>
#include <cuda_bf16.h>

#define N_NODE   100000
#define N_REL    8
#define EMB      32
#define OUT      32
#define NE       1600000
#define BATCH    16384
#define H1       64
#define H2       32
#define H3       16

typedef unsigned long long ull;

// ---------------- scratch (static device globals; no allocation) ----------------
__device__ float  g_w[N_REL * EMB * OUT];               // 32 KB relation weights
__device__ float  g_xh[(size_t)N_NODE * N_REL * OUT];   // 102.4 MB per-(node,rel) transform
__device__ float  g_agg2[(size_t)N_NODE * N_REL * OUT]; // 102.4 MB per-(node,rel) weighted sums
__device__ float  g_denom[N_NODE * N_REL];              // 3.2 MB softmax denominators
__device__ float2 g_dsj[N_NODE * N_REL];                // 6.4 MB {di, sj} per (node,rel)
__device__ int    g_need[N_NODE];                       // 400 KB dst-needed flag
__device__ int    g_nlist[N_NODE];                      // needed-node compact list
__device__ int    g_eseg[NE];                           // compacted dst*8+t
__device__ int    g_esrc[NE];                           // compacted src*8+t
__device__ int    g_cnt;                                // active edge count
__device__ int    g_ncnt;                               // needed node count

// packed f32x2 FMA (Blackwell FFMA2)
__device__ __forceinline__ ull fma2(ull a, ull b, ull c) {
    ull d;
    asm("fma.rn.f32x2 %0, %1, %2, %3;" : "=l"(d) : "l"(a), "l"(b), "l"(c));
    return d;
}

__device__ __forceinline__ void red_add_v4(float* p, float a, float b, float c, float d) {
    asm volatile("red.global.add.v4.f32 [%0], {%1,%2,%3,%4};"
                 :: "l"(p), "f"(a), "f"(b), "f"(c), "f"(d) : "memory");
}

// ---------------- K0: zero denom + need + counters ----------------
__global__ void init_k() {
    int i = blockIdx.x * blockDim.x + threadIdx.x;
    int stride = gridDim.x * blockDim.x;
    for (int j = i; j < N_NODE * N_REL; j += stride) g_denom[j] = 0.f;
    for (int j = i; j < N_NODE; j += stride) g_need[j] = 0;
    if (i == 0) { g_cnt = 0; g_ncnt = 0; }
}

// ---------------- K1: mark needed dst nodes + build compact list ----------------
__global__ void mark_k(const int* __restrict__ users, const int* __restrict__ bundles) {
    int i = blockIdx.x * blockDim.x + threadIdx.x;
    if (i >= 2 * BATCH) return;
    int u = (i < BATCH) ? users[i] : bundles[i - BATCH];
    if (atomicExch(&g_need[u], 1) == 0) {
        int p = atomicAdd(&g_ncnt, 1);
        g_nlist[p] = u;
    }
}

// ---------------- K2: zero agg2 rows of needed nodes (list-based) ----------------
__global__ void zagg_k() {
    int tot = g_ncnt * 64;   // float4s per needed node row
    int stride = gridDim.x * blockDim.x;
    float4 z = make_float4(0.f, 0.f, 0.f, 0.f);
    for (int idx = blockIdx.x * blockDim.x + threadIdx.x; idx < tot; idx += stride) {
        int n = g_nlist[idx >> 6];
        ((float4*)g_agg2)[(size_t)n * 64 + (idx & 63)] = z;
    }
}

// ---------------- K3: w[r][f][o] = sum_b weight[r][b] * basis[b][f][o] ----------------
__global__ void basis_k(const float* __restrict__ weight, const float* __restrict__ basis) {
    int gid = blockIdx.x * 256 + threadIdx.x;   // 8192 threads, one output each
    int r = gid >> 10, fo = gid & 1023;
    float acc = 0.f;
    #pragma unroll
    for (int b = 0; b < 30; b++)
        acc += __ldg(weight + r * 30 + b) * __ldg(basis + b * 1024 + fo);
    g_w[r * 1024 + fo] = acc;
}

// ---------------- K4: xh + fused {di,sj} (FFMA2) ----------------
// block = 256 threads, 128 nodes/block. Main: group g=tid>>7 handles 64 nodes,
// sub=tid&127 -> r=sub>>4, o-pair o2=sub&15; x pre-duplicated {x,x} in shared.
// Epilogue: thread (nl=tid>>1, rbase=(tid&1)*4) computes 4 packed {di,sj} dots.
__global__ void xh_k(const int* __restrict__ x_ids, const float* __restrict__ emb,
                     const float* __restrict__ att) {
    __shared__ float2 xs2[128 * EMB];   // 32 KB
    __shared__ float2 swa[N_REL * EMB]; // 2 KB  {wa1, wa2}
    int tid = threadIdx.x;
    int n0 = blockIdx.x * 128;

    // per-block wa12: thread = (r,f);  wa1 = sum_o w[r,f,o]*att[r,o]; wa2 with att[r,32+o]
    {
        int r = tid >> 5, f = tid & 31;
        const float4* wr = (const float4*)(g_w + (r * EMB + f) * OUT);
        const float* a1 = att + r * 64;
        const float* a2 = a1 + 32;
        float s1 = 0.f, s2 = 0.f;
        #pragma unroll
        for (int q = 0; q < 8; q++) {
            float4 wv = wr[q];
            s1 += wv.x * __ldg(a1 + 4 * q)     + wv.y * __ldg(a1 + 4 * q + 1)
                + wv.z * __ldg(a1 + 4 * q + 2) + wv.w * __ldg(a1 + 4 * q + 3);
            s2 += wv.x * __ldg(a2 + 4 * q)     + wv.y * __ldg(a2 + 4 * q + 1)
                + wv.z * __ldg(a2 + 4 * q + 2) + wv.w * __ldg(a2 + 4 * q + 3);
        }
        swa[r * EMB + f] = make_float2(s1, s2);
    }

    for (int idx = tid; idx < 128 * EMB; idx += 256) {
        int nl = idx >> 5, f = idx & 31;
        int n = n0 + nl;
        float v = (n < N_NODE) ? emb[(size_t)x_ids[n] * EMB + f] : 0.f;
        xs2[idx] = make_float2(v, v);
    }
    __syncthreads();

    int g   = tid >> 7;
    int sub = tid & 127;
    int r   = sub >> 4;
    int o2  = sub & 15;

    ull w2[EMB];
    #pragma unroll
    for (int f = 0; f < EMB; f++)
        w2[f] = *(const ull*)(g_w + (r * EMB + f) * OUT + 2 * o2);

    int gbase = n0 + g * 64;
    int cnt = N_NODE - gbase;
    if (cnt > 64) cnt = 64;

    for (int i = 0; i < cnt; i++) {
        const ull* xp = (const ull*)(xs2 + ((g * 64 + i) << 5));
        ull acc = 0ULL;
        #pragma unroll
        for (int f = 0; f < EMB; f++) acc = fma2(xp[f], w2[f], acc);
        *(ull*)(g_xh + (size_t)(gbase + i) * (N_REL * OUT) + r * OUT + 2 * o2) = acc;
    }

    // fused {di,sj}: 4 relations per thread
    int nl = tid >> 1;
    int rbase = (tid & 1) * 4;
    int n = n0 + nl;
    if (n < N_NODE) {
        const ull* xp = (const ull*)(xs2 + (nl << 5));
        const ull* wap = (const ull*)swa;
        ull acc[4] = {0ULL, 0ULL, 0ULL, 0ULL};
        #pragma unroll
        for (int f = 0; f < EMB; f++) {
            ull xv = xp[f];
            #pragma unroll
            for (int k = 0; k < 4; k++)
                acc[k] = fma2(xv, wap[(rbase + k) * EMB + f], acc[k]);
        }
        #pragma unroll
        for (int k = 0; k < 4; k++)
            *(ull*)(g_dsj + (size_t)n * N_REL + rbase + k) = acc[k];
    }
}

// ---------------- K5: warp-aggregated compaction of active edges ----------------
__global__ void compact_k(const int* __restrict__ ei, const int* __restrict__ et) {
    int e = blockIdx.x * 256 + threadIdx.x;
    int lane = threadIdx.x & 31;
    bool act = false;
    int dst = 0;
    if (e < NE) {
        dst = ei[NE + e];
        act = (g_need[dst] != 0);
    }
    unsigned ballot = __ballot_sync(0xffffffffu, act);
    int nact = __popc(ballot);
    int base = 0;
    if (lane == 0 && nact) base = atomicAdd(&g_cnt, nact);
    base = __shfl_sync(0xffffffffu, base, 0);
    if (act) {
        int src = ei[e];
        int t = et[e];
        int pos = base + __popc(ballot & ((1u << lane) - 1u));
        g_eseg[pos] = dst * N_REL + t;
        g_esrc[pos] = src * N_REL + t;
    }
}

// ---------------- K6: heavy edge pass over compacted list ----------------
__global__ void edge_k() {
    int cnt = g_cnt;
    int stride = gridDim.x * blockDim.x;
    for (int i = blockIdx.x * blockDim.x + threadIdx.x; i < cnt; i += stride) {
        int seg = g_eseg[i];
        int st  = g_esrc[i];
        float di = g_dsj[seg].x;
        float sj = g_dsj[st].y;
        float s = di + sj;
        s = (s > 0.f) ? s : 0.2f * s;
        float ex = __expf(s);
        atomicAdd(&g_denom[seg], ex);
        const float4* hj = (const float4*)(g_xh + (size_t)st * OUT);
        float* p = g_agg2 + (size_t)seg * OUT;
        #pragma unroll
        for (int k = 0; k < 8; k++) {
            float4 v = hj[k];
            red_add_v4(p + 4 * k, v.x * ex, v.y * ex, v.z * ex, v.w * ex);
        }
    }
}

// ---------------- K7: fused combine + node update + 4-layer MLP ----------------
__global__ void mlp_k(const int* __restrict__ users, const int* __restrict__ bundles,
                      const int* __restrict__ x_ids, const float* __restrict__ emb,
                      const float* __restrict__ root, const float* __restrict__ bias,
                      const float* __restrict__ W1, const float* __restrict__ b1,
                      const float* __restrict__ W2, const float* __restrict__ b2,
                      const float* __restrict__ W3, const float* __restrict__ b3,
                      const float* __restrict__ Wo, const float* __restrict__ bo,
                      float* __restrict__ out) {
    __shared__ float sroot[EMB * OUT];
    __shared__ float sW1[2 * OUT * H1];
    __shared__ float sW2[H1 * H2];
    __shared__ float sW3[H2 * H3];
    __shared__ float sWo[H3];
    __shared__ float sbias[OUT], sb1[H1], sb2[H2], sb3[H3];

    int tid = threadIdx.x;
    for (int i = tid; i < EMB * OUT; i += 128) sroot[i] = root[i];
    for (int i = tid; i < 2 * OUT * H1; i += 128) sW1[i] = W1[i];
    for (int i = tid; i < H1 * H2; i += 128) sW2[i] = W2[i];
    for (int i = tid; i < H2 * H3; i += 128) sW3[i] = W3[i];
    if (tid < H3) sWo[tid] = Wo[tid];
    if (tid < OUT) sbias[tid] = bias[tid];
    if (tid < H1) sb1[tid] = b1[tid];
    if (tid < H2) sb2[tid] = b2[tid];
    if (tid < H3) sb3[tid] = b3[tid];
    __syncthreads();

    int b = blockIdx.x * 128 + tid;
    if (b >= BATCH) return;

    int nodes[2];
    nodes[0] = users[b];
    nodes[1] = bundles[b];

    float z[2 * OUT];
    for (int sI = 0; sI < 2; sI++) {
        int n = nodes[sI];
        float hacc[OUT];
        #pragma unroll
        for (int o = 0; o < OUT; o++) hacc[o] = sbias[o];
        const float4* arow = (const float4*)(g_agg2 + (size_t)n * (N_REL * OUT));
        #pragma unroll
        for (int t = 0; t < N_REL; t++) {
            float inv = 1.f / (g_denom[n * N_REL + t] + 1e-16f);
            #pragma unroll
            for (int k = 0; k < 8; k++) {
                float4 v = arow[t * 8 + k];
                hacc[4 * k + 0] += v.x * inv;
                hacc[4 * k + 1] += v.y * inv;
                hacc[4 * k + 2] += v.z * inv;
                hacc[4 * k + 3] += v.w * inv;
            }
        }
        const float* xp = emb + (size_t)x_ids[n] * EMB;
        float xu[EMB];
        #pragma unroll
        for (int f = 0; f < EMB; f++) xu[f] = __ldg(xp + f);
        for (int o = 0; o < OUT; o++) {
            float acc = hacc[o];
            #pragma unroll
            for (int f = 0; f < EMB; f++) acc += xu[f] * sroot[f * OUT + o];
            z[sI * OUT + o] = fmaxf(acc, 0.f);
        }
    }

    float a1[H1];
    for (int j = 0; j < H1; j++) {
        float acc = sb1[j];
        #pragma unroll
        for (int k = 0; k < 2 * OUT; k++) acc += z[k] * sW1[k * H1 + j];
        a1[j] = fmaxf(acc, 0.f);
    }
    float a2[H2];
    for (int j = 0; j < H2; j++) {
        float acc = sb2[j];
        #pragma unroll
        for (int k = 0; k < H1; k++) acc += a1[k] * sW2[k * H2 + j];
        a2[j] = fmaxf(acc, 0.f);
    }
    float a3[H3];
    for (int j = 0; j < H3; j++) {
        float acc = sb3[j];
        #pragma unroll
        for (int k = 0; k < H2; k++) acc += a2[k] * sW3[k * H3 + j];
        a3[j] = fmaxf(acc, 0.f);
    }
    float o = __ldg(bo);
    #pragma unroll
    for (int k = 0; k < H3; k++) o += a3[k] * sWo[k];
    out[b] = o;
}

// ---------------- launch ----------------
extern "C" void kernel_launch(void* const* d_in, const int* in_sizes, int n_in,
                              void* d_out, int out_size) {
    const int*   x_ids      = (const int*)d_in[0];
    const int*   edge_index = (const int*)d_in[1];
    const int*   edge_type  = (const int*)d_in[2];
    const int*   users      = (const int*)d_in[3];
    const int*   bundles    = (const int*)d_in[4];
    const float* emb        = (const float*)d_in[5];
    const float* basis      = (const float*)d_in[6];
    const float* weight     = (const float*)d_in[7];
    const float* att        = (const float*)d_in[8];
    const float* root       = (const float*)d_in[9];
    const float* bias       = (const float*)d_in[10];
    const float* W1         = (const float*)d_in[11];
    const float* b1         = (const float*)d_in[12];
    const float* W2         = (const float*)d_in[13];
    const float* b2         = (const float*)d_in[14];
    const float* W3         = (const float*)d_in[15];
    const float* b3         = (const float*)d_in[16];
    const float* Wo         = (const float*)d_in[17];
    const float* bo         = (const float*)d_in[18];
    float* out = (float*)d_out;

    init_k<<<512, 256>>>();
    mark_k<<<(2 * BATCH + 255) / 256, 256>>>(users, bundles);
    zagg_k<<<1024, 256>>>();
    basis_k<<<32, 256>>>(weight, basis);
    xh_k<<<(N_NODE + 127) / 128, 256>>>(x_ids, emb, att);
    compact_k<<<(NE + 255) / 256, 256>>>(edge_index, edge_type);
    edge_k<<<2048, 256>>>();
    mlp_k<<<BATCH / 128, 128>>>(users, bundles, x_ids, emb, root, bias,
                                W1, b1, W2, b2, W3, b3, Wo, bo, out);
}

// round 7
// speedup vs baseline: 1.2311x; 1.2311x over previous
#include <cuda_runtime.h>
#include <cuda_bf16.h>

#define N_NODE   100000
#define N_REL    8
#define EMB      32
#define OUT      32
#define NE       1600000
#define BATCH    16384
#define H1       64
#define H2       32
#define H3       16

typedef unsigned long long ull;

// ---------------- scratch (static device globals; no allocation) ----------------
__device__ float  g_w[N_REL * EMB * OUT];               // 32 KB relation weights
__device__ float  g_xh[(size_t)N_NODE * N_REL * OUT];   // 102.4 MB per-(node,rel) transform
__device__ float2 g_dsj[N_NODE * N_REL];                // 6.4 MB {di, sj} per (node,rel)
__device__ float  g_h[N_NODE * OUT];                    // 12.8 MB final node features (needed rows only)
__device__ int    g_need[N_NODE];                       // dst-needed flag
__device__ int    g_cntr[N_NODE];                       // per-dst active edge count
__device__ int    g_off[N_NODE];                        // bucket start
__device__ int    g_fill[N_NODE];                       // bucket fill cursor (ends at off+cnt)
__device__ int    g_nlist[N_NODE];                      // compact list of needed nodes
__device__ int    g_ebuf[NE];                           // bucketed payload: src*8+t
__device__ int    g_ncnt;                               // needed node count
__device__ int    g_total;                              // total active edges

// packed f32x2 FMA (Blackwell FFMA2)
__device__ __forceinline__ ull fma2(ull a, ull b, ull c) {
    ull d;
    asm("fma.rn.f32x2 %0, %1, %2, %3;" : "=l"(d) : "l"(a), "l"(b), "l"(c));
    return d;
}

// ---------------- K0: fused basis GEMM (blocks 0..31) + scratch zeroing ----------------
__global__ void initbasis_k(const float* __restrict__ weight, const float* __restrict__ basis) {
    int b = blockIdx.x;
    int tid = threadIdx.x;
    if (b < 32) {
        // w[r][fo] = sum_b weight[r][b] * basis[b][fo]; 8192 outputs over 32 blocks
        int gid = b * 256 + tid;
        int r = gid >> 10, fo = gid & 1023;
        float acc = 0.f;
        #pragma unroll
        for (int k = 0; k < 30; k++)
            acc += __ldg(weight + r * 30 + k) * __ldg(basis + k * 1024 + fo);
        g_w[r * 1024 + fo] = acc;
        if (gid == 0) { g_ncnt = 0; g_total = 0; }
    } else {
        int i = (b - 32) * 256 + tid;
        int stride = (gridDim.x - 32) * 256;
        for (int j = i; j < N_NODE; j += stride) { g_need[j] = 0; g_cntr[j] = 0; }
    }
}

// ---------------- K1: mark needed dst nodes + compact list ----------------
__global__ void mark_k(const int* __restrict__ users, const int* __restrict__ bundles) {
    int i = blockIdx.x * blockDim.x + threadIdx.x;
    if (i >= 2 * BATCH) return;
    int u = (i < BATCH) ? users[i] : bundles[i - BATCH];
    if (atomicExch(&g_need[u], 1) == 0) {
        int p = atomicAdd(&g_ncnt, 1);
        g_nlist[p] = u;
    }
}

// ---------------- K2: xh + fused {di,sj} (FFMA2) ----------------
__global__ void xh_k(const int* __restrict__ x_ids, const float* __restrict__ emb,
                     const float* __restrict__ att) {
    __shared__ float2 xs2[128 * EMB];   // 32 KB x duplicated {x,x}
    __shared__ float2 swa[N_REL * EMB]; // 2 KB  {w@att1, w@att2}
    int tid = threadIdx.x;
    int n0 = blockIdx.x * 128;

    {   // per-block wa: thread=(r,f)
        int r = tid >> 5, f = tid & 31;
        const float4* wr = (const float4*)(g_w + (r * EMB + f) * OUT);
        const float* a1 = att + r * 64;
        const float* a2 = a1 + 32;
        float s1 = 0.f, s2 = 0.f;
        #pragma unroll
        for (int q = 0; q < 8; q++) {
            float4 wv = wr[q];
            s1 += wv.x * __ldg(a1 + 4 * q)     + wv.y * __ldg(a1 + 4 * q + 1)
                + wv.z * __ldg(a1 + 4 * q + 2) + wv.w * __ldg(a1 + 4 * q + 3);
            s2 += wv.x * __ldg(a2 + 4 * q)     + wv.y * __ldg(a2 + 4 * q + 1)
                + wv.z * __ldg(a2 + 4 * q + 2) + wv.w * __ldg(a2 + 4 * q + 3);
        }
        swa[r * EMB + f] = make_float2(s1, s2);
    }

    for (int idx = tid; idx < 128 * EMB; idx += 256) {
        int nl = idx >> 5, f = idx & 31;
        int n = n0 + nl;
        float v = (n < N_NODE) ? emb[(size_t)x_ids[n] * EMB + f] : 0.f;
        xs2[idx] = make_float2(v, v);
    }
    __syncthreads();

    int g   = tid >> 7;
    int sub = tid & 127;
    int r   = sub >> 4;
    int o2  = sub & 15;

    ull w2[EMB];
    #pragma unroll
    for (int f = 0; f < EMB; f++)
        w2[f] = *(const ull*)(g_w + (r * EMB + f) * OUT + 2 * o2);

    int gbase = n0 + g * 64;
    int cnt = N_NODE - gbase;
    if (cnt > 64) cnt = 64;

    for (int i = 0; i < cnt; i++) {
        const ull* xp = (const ull*)(xs2 + ((g * 64 + i) << 5));
        ull acc = 0ULL;
        #pragma unroll
        for (int f = 0; f < EMB; f++) acc = fma2(xp[f], w2[f], acc);
        *(ull*)(g_xh + (size_t)(gbase + i) * (N_REL * OUT) + r * OUT + 2 * o2) = acc;
    }

    // fused {di,sj}: 4 relations per thread
    int nl = tid >> 1;
    int rbase = (tid & 1) * 4;
    int n = n0 + nl;
    if (n < N_NODE) {
        const ull* xp = (const ull*)(xs2 + (nl << 5));
        const ull* wap = (const ull*)swa;
        ull acc[4] = {0ULL, 0ULL, 0ULL, 0ULL};
        #pragma unroll
        for (int f = 0; f < EMB; f++) {
            ull xv = xp[f];
            #pragma unroll
            for (int k = 0; k < 4; k++)
                acc[k] = fma2(xv, wap[(rbase + k) * EMB + f], acc[k]);
        }
        #pragma unroll
        for (int k = 0; k < 4; k++)
            *(ull*)(g_dsj + (size_t)n * N_REL + rbase + k) = acc[k];
    }
}

// ---------------- K3: count active edges per dst ----------------
__global__ void cnt_k(const int* __restrict__ ei) {
    int e = blockIdx.x * 256 + threadIdx.x;
    if (e >= NE) return;
    int dst = ei[NE + e];
    if (g_need[dst]) atomicAdd(&g_cntr[dst], 1);
}

// ---------------- K4: bucket offset allocation (warp-aggregated) ----------------
__global__ void off_k() {
    int n = blockIdx.x * 256 + threadIdx.x;
    int lane = threadIdx.x & 31;
    bool act = (n < N_NODE) && g_need[n];
    int c = act ? g_cntr[n] : 0;
    // inclusive warp scan
    int incl = c;
    #pragma unroll
    for (int d = 1; d < 32; d <<= 1) {
        int v = __shfl_up_sync(0xffffffffu, incl, d);
        if (lane >= d) incl += v;
    }
    int tot = __shfl_sync(0xffffffffu, incl, 31);
    int base = 0;
    if (lane == 31 && tot) base = atomicAdd(&g_total, tot);
    base = __shfl_sync(0xffffffffu, base, 31);
    if (act) {
        int off = base + incl - c;
        g_off[n] = off;
        g_fill[n] = off;
    }
}

// ---------------- K5: fill buckets with src*8+t ----------------
__global__ void fill_k(const int* __restrict__ ei, const int* __restrict__ et) {
    int e = blockIdx.x * 256 + threadIdx.x;
    if (e >= NE) return;
    int dst = ei[NE + e];
    if (!g_need[dst]) return;
    int pos = atomicAdd(&g_fill[dst], 1);
    g_ebuf[pos] = ei[e] * N_REL + et[e];
}

// ---------------- K6: per-node gather aggregation (warp per node), no atomics ----------------
__global__ void nodeagg_k(const int* __restrict__ x_ids, const float* __restrict__ emb,
                          const float* __restrict__ root, const float* __restrict__ bias) {
    __shared__ float sroot[EMB * OUT];       // 4 KB
    __shared__ float sagg[8][N_REL * OUT];   // 8 KB/warp-row total 32 KB... (8 warps x 1KB)
    __shared__ float sden[8][N_REL];

    int tid = threadIdx.x;
    int wid = tid >> 5, lane = tid & 31;
    for (int i = tid; i < EMB * OUT; i += 256) sroot[i] = root[i];

    // zero per-warp accumulators (warp-private, no sync needed before use)
    #pragma unroll
    for (int i = 0; i < 8; i++) sagg[wid][i * 32 + lane] = 0.f;
    if (lane < N_REL) sden[wid][lane] = 0.f;

    int widx = blockIdx.x * 8 + wid;
    bool act = (widx < g_ncnt);
    int n = 0, e0 = 0, e1 = 0;
    if (act) {
        n = g_nlist[widx];
        e0 = g_off[n];
        e1 = g_fill[n];
    }

    __syncthreads();   // sroot ready (also after this, warp-private smem is fine)

    if (act) {
        for (int e = e0; e < e1; e++) {
            int st = __ldg(&g_ebuf[e]);
            int t = st & 7;
            float di = __ldg(&((const float*)g_dsj)[(n * N_REL + t) * 2]);
            float sj = __ldg(&((const float*)g_dsj)[st * 2 + 1]);
            float s = di + sj;
            s = (s > 0.f) ? s : 0.2f * s;
            float ex = __expf(s);
            float hj = __ldg(&g_xh[(size_t)st * OUT + lane]);
            sagg[wid][t * 32 + lane] += hj * ex;
            if (lane == t) sden[wid][t] += ex;
        }
        // finalize: h = relu(sum_t agg/den + x@root + bias)
        float acc = __ldg(&bias[lane]);
        #pragma unroll
        for (int t = 0; t < N_REL; t++)
            acc += sagg[wid][t * 32 + lane] / (sden[wid][t] + 1e-16f);
        float xv = __ldg(&emb[(size_t)x_ids[n] * EMB + lane]);
        #pragma unroll
        for (int f = 0; f < EMB; f++)
            acc += __shfl_sync(0xffffffffu, xv, f) * sroot[f * OUT + lane];
        g_h[n * OUT + lane] = fmaxf(acc, 0.f);
    }
}

// ---------------- K7: MLP over (user,bundle) pairs ----------------
__global__ void mlp_k(const int* __restrict__ users, const int* __restrict__ bundles,
                      const float* __restrict__ W1, const float* __restrict__ b1,
                      const float* __restrict__ W2, const float* __restrict__ b2,
                      const float* __restrict__ W3, const float* __restrict__ b3,
                      const float* __restrict__ Wo, const float* __restrict__ bo,
                      float* __restrict__ out) {
    __shared__ float sW1[2 * OUT * H1];
    __shared__ float sW2[H1 * H2];
    __shared__ float sW3[H2 * H3];
    __shared__ float sWo[H3];
    __shared__ float sb1[H1], sb2[H2], sb3[H3];

    int tid = threadIdx.x;
    for (int i = tid; i < 2 * OUT * H1; i += 128) sW1[i] = W1[i];
    for (int i = tid; i < H1 * H2; i += 128) sW2[i] = W2[i];
    for (int i = tid; i < H2 * H3; i += 128) sW3[i] = W3[i];
    if (tid < H3) sWo[tid] = Wo[tid];
    if (tid < H1) sb1[tid] = b1[tid];
    if (tid < H2) sb2[tid] = b2[tid];
    if (tid < H3) sb3[tid] = b3[tid];
    __syncthreads();

    int b = blockIdx.x * 128 + tid;
    if (b >= BATCH) return;

    int nu = users[b], nb = bundles[b];
    float z[2 * OUT];
    const float4* hu = (const float4*)(g_h + (size_t)nu * OUT);
    const float4* hb = (const float4*)(g_h + (size_t)nb * OUT);
    #pragma unroll
    for (int k = 0; k < 8; k++) {
        float4 v = hu[k];
        z[4 * k] = v.x; z[4 * k + 1] = v.y; z[4 * k + 2] = v.z; z[4 * k + 3] = v.w;
    }
    #pragma unroll
    for (int k = 0; k < 8; k++) {
        float4 v = hb[k];
        z[32 + 4 * k] = v.x; z[32 + 4 * k + 1] = v.y; z[32 + 4 * k + 2] = v.z; z[32 + 4 * k + 3] = v.w;
    }

    float a1[H1];
    for (int j = 0; j < H1; j++) {
        float acc = sb1[j];
        #pragma unroll
        for (int k = 0; k < 2 * OUT; k++) acc += z[k] * sW1[k * H1 + j];
        a1[j] = fmaxf(acc, 0.f);
    }
    float a2[H2];
    for (int j = 0; j < H2; j++) {
        float acc = sb2[j];
        #pragma unroll
        for (int k = 0; k < H1; k++) acc += a1[k] * sW2[k * H2 + j];
        a2[j] = fmaxf(acc, 0.f);
    }
    float a3[H3];
    for (int j = 0; j < H3; j++) {
        float acc = sb3[j];
        #pragma unroll
        for (int k = 0; k < H2; k++) acc += a2[k] * sW3[k * H3 + j];
        a3[j] = fmaxf(acc, 0.f);
    }
    float o = __ldg(bo);
    #pragma unroll
    for (int k = 0; k < H3; k++) o += a3[k] * sWo[k];
    out[b] = o;
}

// ---------------- launch ----------------
extern "C" void kernel_launch(void* const* d_in, const int* in_sizes, int n_in,
                              void* d_out, int out_size) {
    const int*   x_ids      = (const int*)d_in[0];
    const int*   edge_index = (const int*)d_in[1];
    const int*   edge_type  = (const int*)d_in[2];
    const int*   users      = (const int*)d_in[3];
    const int*   bundles    = (const int*)d_in[4];
    const float* emb        = (const float*)d_in[5];
    const float* basis      = (const float*)d_in[6];
    const float* weight     = (const float*)d_in[7];
    const float* att        = (const float*)d_in[8];
    const float* root       = (const float*)d_in[9];
    const float* bias       = (const float*)d_in[10];
    const float* W1         = (const float*)d_in[11];
    const float* b1         = (const float*)d_in[12];
    const float* W2         = (const float*)d_in[13];
    const float* b2         = (const float*)d_in[14];
    const float* W3         = (const float*)d_in[15];
    const float* b3         = (const float*)d_in[16];
    const float* Wo         = (const float*)d_in[17];
    const float* bo         = (const float*)d_in[18];
    float* out = (float*)d_out;

    initbasis_k<<<32 + 256, 256>>>(weight, basis);
    mark_k<<<(2 * BATCH + 255) / 256, 256>>>(users, bundles);
    xh_k<<<(N_NODE + 127) / 128, 256>>>(x_ids, emb, att);
    cnt_k<<<(NE + 255) / 256, 256>>>(edge_index);
    off_k<<<(N_NODE + 255) / 256, 256>>>();
    fill_k<<<(NE + 255) / 256, 256>>>(edge_index, edge_type);
    nodeagg_k<<<(2 * BATCH + 7) / 8, 256>>>(x_ids, emb, root, bias);
    mlp_k<<<BATCH / 128, 128>>>(users, bundles,
                                W1, b1, W2, b2, W3, b3, Wo, bo, out);
}